// round 1
// baseline (speedup 1.0000x reference)
#include <cuda_runtime.h>
#include <cstdint>

// Depthwise 3x3 conv, stride 1, VALID, C=64.
// x: (16, 64, 512, 512) f32, w: (64, 3, 3) f32 -> out: (16, 64, 510, 510) f32
//
// Strategy: memory-roofline kernel, no shared memory (smem crossbar would be
// the bottleneck at 9 reads/output). Each thread owns 4 output columns and
// rolls a 3-row register window down a TILE_H-row tile. Math uses packed
// fma.rn.f32x2 (FFMA2) because scalar FFMA (rt=2/SMSP) would be compute-bound
// above the HBM floor on sm_103a.

#define TILE_H 10   // 510 = 51 * 10
#define THREADS 128 // 128 threads * 4 cols = 512 >= 510

typedef unsigned long long u64;

__device__ __forceinline__ u64 fpack2(float lo, float hi) {
    u64 d;
    asm("mov.b64 %0, {%1, %2};" : "=l"(d) : "f"(lo), "f"(hi));
    return d;
}

__device__ __forceinline__ u64 fmul2(u64 a, u64 b) {
    u64 d;
    asm("mul.rn.f32x2 %0, %1, %2;" : "=l"(d) : "l"(a), "l"(b));
    return d;
}

__device__ __forceinline__ u64 ffma2(u64 a, u64 b, u64 c) {
    u64 d;
    asm("fma.rn.f32x2 %0, %1, %2, %3;" : "=l"(d) : "l"(a), "l"(b), "l"(c));
    return d;
}

// Load 6 consecutive floats starting at p (16B aligned) and form the 5
// overlapping f32x2 pairs (v0,v1) (v1,v2) (v2,v3) (v3,v4) (v4,v5).
// If `last` (thread covering cols 508..511), cols 512/513 may be OOB at the
// image end; zero them (they only feed the two invalid outputs 510/511).
__device__ __forceinline__ void load_row_pairs(const float* __restrict__ p,
                                               bool last, u64 q[5]) {
    float4 a = *reinterpret_cast<const float4*>(p);
    float v4 = 0.0f, v5 = 0.0f;
    if (!last) {
        float2 b = *reinterpret_cast<const float2*>(p + 4);
        v4 = b.x;
        v5 = b.y;
    }
    q[0] = fpack2(a.x, a.y);
    q[1] = fpack2(a.y, a.z);
    q[2] = fpack2(a.z, a.w);
    q[3] = fpack2(a.w, v4);
    q[4] = fpack2(v4, v5);
}

__global__ void __launch_bounds__(THREADS)
dwconv3x3_kernel(const float* __restrict__ x,
                 const float* __restrict__ w,
                 float* __restrict__ out) {
    const int tile = blockIdx.x;   // 0..50
    const int c    = blockIdx.y;   // 0..63
    const int n    = blockIdx.z;   // 0..15

    const int tid = threadIdx.x;
    const int x0  = tid * 4;               // first owned output column
    const bool last = (x0 == 508);         // thread 127: only cols 508,509 valid

    const size_t img_off = ((size_t)(n * 64 + c)) * (512 * 512);
    const size_t out_off = ((size_t)(n * 64 + c)) * (510 * 510);
    const float* img = x + img_off;
    float* o = out + out_off;

    const int r0 = tile * TILE_H;          // first output row of this tile

    // Broadcast weights as (w,w) f32x2 pairs.
    const float* wc = w + c * 9;
    u64 wp[9];
#pragma unroll
    for (int i = 0; i < 9; ++i) {
        float wv = __ldg(wc + i);
        wp[i] = fpack2(wv, wv);
    }

    // Rolling 3-row window of overlapping pairs.
    u64 q[3][5];
    load_row_pairs(img + (size_t)(r0 + 0) * 512 + x0, last, q[0]);
    load_row_pairs(img + (size_t)(r0 + 1) * 512 + x0, last, q[1]);

#pragma unroll
    for (int r = 0; r < TILE_H; ++r) {
        const int top = r % 3;
        const int mid = (r + 1) % 3;
        const int bot = (r + 2) % 3;

        load_row_pairs(img + (size_t)(r0 + r + 2) * 512 + x0, last, q[bot]);

        // outputs (x0, x0+1)
        u64 acc01 = fmul2(wp[0], q[top][0]);
        acc01 = ffma2(wp[1], q[top][1], acc01);
        acc01 = ffma2(wp[2], q[top][2], acc01);
        acc01 = ffma2(wp[3], q[mid][0], acc01);
        acc01 = ffma2(wp[4], q[mid][1], acc01);
        acc01 = ffma2(wp[5], q[mid][2], acc01);
        acc01 = ffma2(wp[6], q[bot][0], acc01);
        acc01 = ffma2(wp[7], q[bot][1], acc01);
        acc01 = ffma2(wp[8], q[bot][2], acc01);

        // outputs (x0+2, x0+3)
        u64 acc23 = fmul2(wp[0], q[top][2]);
        acc23 = ffma2(wp[1], q[top][3], acc23);
        acc23 = ffma2(wp[2], q[top][4], acc23);
        acc23 = ffma2(wp[3], q[mid][2], acc23);
        acc23 = ffma2(wp[4], q[mid][3], acc23);
        acc23 = ffma2(wp[5], q[mid][4], acc23);
        acc23 = ffma2(wp[6], q[bot][2], acc23);
        acc23 = ffma2(wp[7], q[bot][3], acc23);
        acc23 = ffma2(wp[8], q[bot][4], acc23);

        // Row stride 510*4 = 2040 B is only 8-byte aligned -> STG.64 stores.
        float* orow = o + (size_t)(r0 + r) * 510 + x0;
        *reinterpret_cast<u64*>(orow) = acc01;
        if (!last) {
            *reinterpret_cast<u64*>(orow + 2) = acc23;
        }
    }
}

extern "C" void kernel_launch(void* const* d_in, const int* in_sizes, int n_in,
                              void* d_out, int out_size) {
    const float* x = (const float*)d_in[0];
    const float* w = (const float*)d_in[1];
    // Defensive: metadata order is (x, weight); swap if sizes say otherwise.
    if (n_in >= 2 && in_sizes[0] < in_sizes[1]) {
        const float* t = x; x = w; w = t;
    }
    float* out = (float*)d_out;

    dim3 grid(51, 64, 16); // 510/TILE_H row tiles, C, N
    dwconv3x3_kernel<<<grid, THREADS>>>(x, w, out);
}